// round 2
// baseline (speedup 1.0000x reference)
#include <cuda_runtime.h>
#include <math.h>

// Problem constants (fixed by setup_inputs)
#define BB 4
#define LL 2048
#define HH 8
#define DD 64
#define SS 40            // samples per query
#define UU 40            // top-k queries
#define SCALE 0.125f     // 1/sqrt(64)

// kernel3 (attention) config
#define K3_CHUNK 64
#define K3_NCH (LL / K3_CHUNK)   // 32
#define K3_T 128

// kernel4 (cumsum) config
#define K4_NC 16
#define K4_CLEN (LL / K4_NC)     // 128

// ---------------- scratch (static device globals; no runtime alloc) ----------------
__device__ float g_M[BB*HH*LL];                       // 256 KB
__device__ int   g_Mtop[BB*HH*UU];                    // 5 KB
__device__ int   g_sel[BB*HH*LL];                     // 256 KB
__device__ float g_upd[BB*HH*UU*DD];                  // 327 KB
__device__ float g_pm[BB*HH*K3_NCH*UU];               // partial row max
__device__ float g_pl[BB*HH*K3_NCH*UU];               // partial exp-sum
__device__ float g_pacc[(size_t)BB*HH*K3_NCH*UU*DD];  // ~10.5 MB partial AV
__device__ float g_csum[BB*K4_NC*HH*DD];              // chunk sums for cumsum

// ================= Kernel 1: sparsity measure M =================
// One warp per (b,h,l). Q row in float2 regs; gather 40 K rows, dot, track max & sum.
__global__ void k_M(const float* __restrict__ Q, const float* __restrict__ K,
                    const int* __restrict__ idx) {
    int warp = (blockIdx.x * blockDim.x + threadIdx.x) >> 5;
    int lane = threadIdx.x & 31;
    // warp in [0, BB*HH*LL) exactly
    int l  = warp % LL;
    int bh = warp / LL;
    int h  = bh % HH;
    int b  = bh / HH;

    const float2 q = *(const float2*)(Q + ((b*LL + l)*HH + h)*DD + 2*lane);
    float maxv = -INFINITY, sum = 0.f;
    const int* row = idx + l*SS;
    #pragma unroll 8
    for (int s = 0; s < SS; s++) {
        int j = __ldg(row + s);
        const float2 k = *(const float2*)(K + ((b*LL + j)*HH + h)*DD + 2*lane);
        float p = q.x*k.x + q.y*k.y;
        p += __shfl_xor_sync(0xffffffffu, p, 16);
        p += __shfl_xor_sync(0xffffffffu, p, 8);
        p += __shfl_xor_sync(0xffffffffu, p, 4);
        p += __shfl_xor_sync(0xffffffffu, p, 2);
        p += __shfl_xor_sync(0xffffffffu, p, 1);
        maxv = fmaxf(maxv, p);
        sum += p;
    }
    if (lane == 0)
        g_M[(b*HH + h)*LL + l] = maxv - sum * (1.0f / (float)LL);
}

// ================= Kernel 2: top-U selection per (b,h) =================
// Iterative argmax (40 rounds), jax tie-break = lowest index. Also builds sel map.
__global__ void k_topk() {
    int bh = blockIdx.x;
    __shared__ float vals[LL];
    __shared__ float rv[256];
    __shared__ int   ri[256];
    for (int i = threadIdx.x; i < LL; i += 256) {
        vals[i] = g_M[bh*LL + i];
        g_sel[bh*LL + i] = -1;
    }
    __syncthreads();
    for (int u = 0; u < UU; u++) {
        float bv = -INFINITY; int bi = 0x7fffffff;
        for (int i = threadIdx.x; i < LL; i += 256) {
            float v = vals[i];
            if (v > bv || (v == bv && i < bi)) { bv = v; bi = i; }
        }
        rv[threadIdx.x] = bv; ri[threadIdx.x] = bi;
        __syncthreads();
        for (int off = 128; off; off >>= 1) {
            if (threadIdx.x < off) {
                float ov = rv[threadIdx.x + off]; int oi = ri[threadIdx.x + off];
                if (ov > rv[threadIdx.x] ||
                    (ov == rv[threadIdx.x] && oi < ri[threadIdx.x])) {
                    rv[threadIdx.x] = ov; ri[threadIdx.x] = oi;
                }
            }
            __syncthreads();
        }
        if (threadIdx.x == 0) {
            int sel = ri[0];
            g_Mtop[bh*UU + u] = sel;
            g_sel[bh*LL + sel] = u;
            vals[sel] = -INFINITY;
        }
        __syncthreads();
    }
}

// ================= Kernel 3: split-K attention partials =================
// block = (kchunk c, bh). K/V each read once per (b,h). Per-chunk softmax partials.
__global__ void __launch_bounds__(K3_T)
k_attn_partial(const float* __restrict__ Q, const float* __restrict__ K,
               const float* __restrict__ V) {
    __shared__ __align__(16) float Qs[UU*68];          // padded rows (17 float4)
    __shared__ __align__(16) float Ks[K3_CHUNK*68];    // K chunk, then reused for V
    __shared__ __align__(16) float psm[K3_CHUNK*44];   // scores [k][u], 11 float4/row
    __shared__ float sm_m[UU];

    int c  = blockIdx.x;           // k-chunk
    int bh = blockIdx.y;
    int b = bh >> 3, h = bh & 7;
    int tid = threadIdx.x;
    int k0 = c * K3_CHUNK;

    // load Q_reduce rows (gathered by Mtop)
    for (int i = tid; i < UU*DD; i += K3_T) {
        int u = i >> 6, d = i & 63;
        int l = g_Mtop[bh*UU + u];
        Qs[u*68 + d] = Q[((b*LL + l)*HH + h)*DD + d];
    }
    // load K chunk
    for (int i = tid; i < K3_CHUNK*DD; i += K3_T) {
        int k = i >> 6, d = i & 63;
        Ks[k*68 + d] = K[((b*LL + k0 + k)*HH + h)*DD + d];
    }
    __syncthreads();

    // ---- scores: thread owns (k = tid&63, ug = tid>>6 -> 20 u's) ----
    {
        int kk = tid & 63;
        int ug = tid >> 6;
        float acc[20];
        #pragma unroll
        for (int u = 0; u < 20; u++) acc[u] = 0.f;
        const float4* K4 = (const float4*)Ks;
        const float4* Q4 = (const float4*)Qs;
        #pragma unroll
        for (int d4 = 0; d4 < 16; d4++) {
            float4 kv = K4[kk*17 + d4];
            #pragma unroll
            for (int u = 0; u < 20; u++) {
                float4 qv = Q4[(ug*20 + u)*17 + d4];
                acc[u] += kv.x*qv.x + kv.y*qv.y + kv.z*qv.z + kv.w*qv.w;
            }
        }
        #pragma unroll
        for (int u = 0; u < 20; u++)
            psm[kk*44 + ug*20 + u] = acc[u] * SCALE;
    }
    __syncthreads();

    // ---- per-u chunk max ----
    if (tid < UU) {
        float m = -INFINITY;
        for (int k = 0; k < K3_CHUNK; k++) m = fmaxf(m, psm[k*44 + tid]);
        sm_m[tid] = m;
    }
    __syncthreads();
    // exponentiate in place
    for (int i = tid; i < K3_CHUNK*UU; i += K3_T) {
        int k = i / UU, u = i - k*UU;
        psm[k*44 + u] = __expf(psm[k*44 + u] - sm_m[u]);
    }
    __syncthreads();
    // load V chunk (reuse Ks) while 40 threads compute exp-sums
    for (int i = tid; i < K3_CHUNK*DD; i += K3_T) {
        int k = i >> 6, d = i & 63;
        Ks[k*68 + d] = V[((b*LL + k0 + k)*HH + h)*DD + d];
    }
    if (tid < UU) {
        float s = 0.f;
        for (int k = 0; k < K3_CHUNK; k++) s += psm[k*44 + tid];
        int pidx = (bh*K3_NCH + c)*UU + tid;
        g_pm[pidx] = sm_m[tid];
        g_pl[pidx] = s;
    }
    __syncthreads();

    // ---- AV: thread owns (d = tid&63, kg = tid>>6 -> 32 k's) ----
    {
        int d  = tid & 63;
        int kg = tid >> 6;
        float4 oacc[10];
        #pragma unroll
        for (int i = 0; i < 10; i++) oacc[i] = make_float4(0.f, 0.f, 0.f, 0.f);
        const float4* P4 = (const float4*)psm;
        #pragma unroll
        for (int k2 = 0; k2 < 32; k2++) {
            int krow = kg*32 + k2;
            float vv = Ks[krow*68 + d];
            #pragma unroll
            for (int u4 = 0; u4 < 10; u4++) {
                float4 p = P4[krow*11 + u4];
                oacc[u4].x += p.x*vv; oacc[u4].y += p.y*vv;
                oacc[u4].z += p.z*vv; oacc[u4].w += p.w*vv;
            }
        }
        __syncthreads();
        float* red = Qs;  // Qs free now; reuse as [u][64] reduce buffer
        if (kg == 1) {
            #pragma unroll
            for (int u4 = 0; u4 < 10; u4++) {
                red[(u4*4+0)*64 + d] = oacc[u4].x;
                red[(u4*4+1)*64 + d] = oacc[u4].y;
                red[(u4*4+2)*64 + d] = oacc[u4].z;
                red[(u4*4+3)*64 + d] = oacc[u4].w;
            }
        }
        __syncthreads();
        if (kg == 0) {
            float* dst = g_pacc + ((size_t)(bh*K3_NCH + c)*UU)*DD;
            #pragma unroll
            for (int u4 = 0; u4 < 10; u4++) {
                dst[(u4*4+0)*64 + d] = oacc[u4].x + red[(u4*4+0)*64 + d];
                dst[(u4*4+1)*64 + d] = oacc[u4].y + red[(u4*4+1)*64 + d];
                dst[(u4*4+2)*64 + d] = oacc[u4].z + red[(u4*4+2)*64 + d];
                dst[(u4*4+3)*64 + d] = oacc[u4].w + red[(u4*4+3)*64 + d];
            }
        }
    }
}

// ================= Kernel 3b: combine chunk partials (LSE merge) =================
__global__ void k_combine() {
    int bhu = blockIdx.x;
    int u  = bhu % UU;
    int bh = bhu / UU;
    int d  = threadIdx.x;
    float m = -INFINITY;
    #pragma unroll
    for (int c = 0; c < K3_NCH; c++)
        m = fmaxf(m, g_pm[(bh*K3_NCH + c)*UU + u]);
    float lsum = 0.f, val = 0.f;
    for (int c = 0; c < K3_NCH; c++) {
        int pidx = (bh*K3_NCH + c)*UU + u;
        float w = __expf(g_pm[pidx] - m);
        lsum += g_pl[pidx] * w;
        val  += g_pacc[(size_t)pidx*DD + d] * w;
    }
    g_upd[(bh*UU + u)*DD + d] = val / lsum;
}

// ================= Kernel 4a: per-chunk sums of V along L =================
__global__ void k_csum(const float* __restrict__ V) {
    int b = blockIdx.x >> 4;     // K4_NC = 16
    int c = blockIdx.x & 15;
    int hd = threadIdx.x;        // 512 threads = H*D
    const float* p = V + ((size_t)(b*LL + c*K4_CLEN))*512 + hd;
    float s = 0.f;
    #pragma unroll 8
    for (int i = 0; i < K4_CLEN; i++) s += p[i*512];
    g_csum[(b*K4_NC + c)*512 + hd] = s;
}

// ================= Kernel 4b: cumsum + scatter upd -> output =================
__global__ void k_out(const float* __restrict__ V, float* __restrict__ out) {
    int b = blockIdx.x >> 4;
    int c = blockIdx.x & 15;
    int hd = threadIdx.x;
    int h = hd >> 6, d = hd & 63;
    float acc = 0.f;
    for (int cc = 0; cc < c; cc++) acc += g_csum[(b*K4_NC + cc)*512 + hd];
    const float* p = V   + ((size_t)(b*LL + c*K4_CLEN))*512 + hd;
    float*       q = out + ((size_t)(b*LL + c*K4_CLEN))*512 + hd;
    const int* sel = g_sel + (b*HH + h)*LL + c*K4_CLEN;
    for (int i = 0; i < K4_CLEN; i++) {
        acc += p[i*512];
        int se = sel[i];
        float v = acc;
        if (se >= 0) v = g_upd[((b*HH + h)*UU + se)*DD + d];
        q[i*512] = v;
    }
}

// ================= launch =================
extern "C" void kernel_launch(void* const* d_in, const int* in_sizes, int n_in,
                              void* d_out, int out_size) {
    const float* Q  = (const float*)d_in[0];
    const float* K  = (const float*)d_in[1];
    const float* V  = (const float*)d_in[2];
    const int* idx  = (const int*)d_in[3];
    float* out = (float*)d_out;

    k_M<<<(BB*HH*LL)/8, 256>>>(Q, K, idx);          // 65536 warps
    k_topk<<<BB*HH, 256>>>();
    dim3 g3(K3_NCH, BB*HH);
    k_attn_partial<<<g3, K3_T>>>(Q, K, V);
    k_combine<<<BB*HH*UU, DD>>>();
    k_csum<<<BB*K4_NC, 512>>>(V);
    k_out<<<BB*K4_NC, 512>>>(V, out);
}

// round 3
// speedup vs baseline: 1.7593x; 1.7593x over previous
#include <cuda_runtime.h>
#include <math.h>

// Problem constants (fixed by setup_inputs)
#define BB 4
#define LL 2048
#define HH 8
#define DD 64
#define SS 40            // samples per query
#define UU 40            // top-k queries
#define SCALE 0.125f     // 1/sqrt(64)

// kernel3 (attention) config
#define K3_CHUNK 64
#define K3_NCH (LL / K3_CHUNK)   // 32
#define K3_T 128

// kernel4 (cumsum) config
#define K4_NC 16
#define K4_CLEN (LL / K4_NC)     // 128

// ---------------- scratch (static device globals; no runtime alloc) ----------------
__device__ float g_M[BB*HH*LL];
__device__ int   g_Mtop[BB*HH*UU];
__device__ int   g_sel[BB*HH*LL];
__device__ float g_upd[BB*HH*UU*DD];
__device__ float g_pm[BB*HH*K3_NCH*UU];
__device__ float g_pl[BB*HH*K3_NCH*UU];
__device__ float g_pacc[(size_t)BB*HH*K3_NCH*UU*DD];
__device__ float g_csum[BB*K4_NC*HH*DD];

// ================= Kernel 1: sparsity measure M (v2: smem-staged, no per-s shuffles) ====
// Block = 256 threads, handles 4 queries. Gather 160 K rows to smem (coalesced per row),
// one thread per (query, sample) dot, then one 5-level shfl reduce per query.
__global__ void __launch_bounds__(256)
k_M(const float* __restrict__ Q, const float* __restrict__ K,
    const int* __restrict__ idx) {
    __shared__ float sQ[4*64];
    __shared__ __align__(16) float sK[160*68];   // 160 rows, 17-f4 pitch
    __shared__ int   sIdx[160];
    __shared__ float dots[160];

    int bh = blockIdx.x >> 9;            // 512 blocks per (b,h)
    int l0 = (blockIdx.x & 511) << 2;
    int h = bh & 7, b = bh >> 3;
    int t = threadIdx.x;

    if (t < 160) sIdx[t] = idx[l0*SS + t];            // 4 idx rows, contiguous
    { int li = t >> 6, d = t & 63;
      sQ[t] = Q[((b*LL + l0 + li)*HH + h)*DD + d]; }
    __syncthreads();

    const float4* K4g = (const float4*)K;
    float4* sK4 = (float4*)sK;
    #pragma unroll
    for (int it = 0; it < 10; it++) {                 // 2560 float4s
        int i  = t + it*256;
        int r  = i >> 4, d4 = i & 15;
        int j  = sIdx[r];
        sK4[r*17 + d4] = K4g[((b*LL + j)*HH + h)*16 + d4];
    }
    __syncthreads();

    if (t < 160) {
        int li = t / 40, s = t - li*40;
        const float4* q4 = (const float4*)(sQ + li*64);
        const float4* k4 = sK4 + (li*40 + s)*17;
        float acc = 0.f;
        #pragma unroll
        for (int d4 = 0; d4 < 16; d4++) {
            float4 q = q4[d4], k = k4[d4];
            acc += q.x*k.x + q.y*k.y + q.z*k.z + q.w*k.w;
        }
        dots[li*40 + s] = acc;
    }
    __syncthreads();

    int w = t >> 5, lane = t & 31;
    if (w < 4) {
        float a  = dots[w*40 + lane];
        float b2 = (lane < 8) ? dots[w*40 + 32 + lane] : 0.f;
        float m  = (lane < 8) ? fmaxf(a, b2) : a;
        float sm = a + b2;
        #pragma unroll
        for (int off = 16; off; off >>= 1) {
            m  = fmaxf(m, __shfl_xor_sync(0xffffffffu, m, off));
            sm += __shfl_xor_sync(0xffffffffu, sm, off);
        }
        if (lane == 0) g_M[bh*LL + l0 + w] = m - sm * (1.0f/(float)LL);
    }
}

// ================= Kernel 2: top-U per (b,h) (v2: register-resident, 2 syncs/round) ====
__global__ void __launch_bounds__(256) k_topk() {
    int bh = blockIdx.x;
    int t = threadIdx.x;
    int lane = t & 31, w = t >> 5;
    float v[8];
    __shared__ float rv[8];
    __shared__ int   ri[8];
    __shared__ int   ssel;
    #pragma unroll
    for (int j = 0; j < 8; j++) {
        int i = t + 256*j;
        v[j] = g_M[bh*LL + i];
        g_sel[bh*LL + i] = -1;
    }
    for (int u = 0; u < UU; u++) {
        float lv = v[0]; int li = t;
        #pragma unroll
        for (int j = 1; j < 8; j++)
            if (v[j] > lv) { lv = v[j]; li = t + 256*j; }
        #pragma unroll
        for (int off = 16; off; off >>= 1) {
            float ov = __shfl_xor_sync(0xffffffffu, lv, off);
            int   oi = __shfl_xor_sync(0xffffffffu, li, off);
            if (ov > lv || (ov == lv && oi < li)) { lv = ov; li = oi; }
        }
        if (lane == 0) { rv[w] = lv; ri[w] = li; }
        __syncthreads();
        if (t == 0) {
            float bv = rv[0]; int bi = ri[0];
            #pragma unroll
            for (int k = 1; k < 8; k++)
                if (rv[k] > bv || (rv[k] == bv && ri[k] < bi)) { bv = rv[k]; bi = ri[k]; }
            ssel = bi;
            g_Mtop[bh*UU + u] = bi;
            g_sel[bh*LL + bi] = u;
        }
        __syncthreads();
        int sel = ssel;
        if ((sel & 255) == t) v[sel >> 8] = -INFINITY;
    }
}

// ================= Kernel 3: split-K attention partials (v2 tiling) ====
// Score: thread = (ug=tid&7 -> 5 u, kg=tid>>3 -> 4 k): K loads broadcast per phase,
// Q loads conflict-free. AV: thread = (dg=tid&15 -> 4 d, ug -> 5 u), owns full k-range
// (no cross-thread reduction).
__global__ void __launch_bounds__(K3_T)
k_attn_partial(const float* __restrict__ Q, const float* __restrict__ K,
               const float* __restrict__ V) {
    __shared__ __align__(16) float Qs[UU*68];
    __shared__ __align__(16) float Ks[K3_CHUNK*68];
    __shared__ __align__(16) float psm[K3_CHUNK*44];
    __shared__ float sm_m[UU];

    int c = blockIdx.x, bh = blockIdx.y;
    int b = bh >> 3, h = bh & 7;
    int tid = threadIdx.x;
    int k0 = c * K3_CHUNK;
    const float4* Qg = (const float4*)Q;
    const float4* Kg = (const float4*)K;
    const float4* Vg = (const float4*)V;
    float4* Qs4 = (float4*)Qs;
    float4* Ks4 = (float4*)Ks;

    #pragma unroll
    for (int it = 0; it < 5; it++) {                  // Q_reduce: 640 f4
        int i = tid + it*128;
        int u = i >> 4, d4 = i & 15;
        int l = g_Mtop[bh*UU + u];
        Qs4[u*17 + d4] = Qg[((b*LL + l)*HH + h)*16 + d4];
    }
    #pragma unroll
    for (int it = 0; it < 8; it++) {                  // K chunk: 1024 f4
        int i = tid + it*128;
        int k = i >> 4, d4 = i & 15;
        Ks4[k*17 + d4] = Kg[((b*LL + k0 + k)*HH + h)*16 + d4];
    }
    __syncthreads();

    // ---- scores ----
    {
        int ug = tid & 7, kg = tid >> 3;
        float acc[4][5];
        #pragma unroll
        for (int a = 0; a < 4; a++)
            #pragma unroll
            for (int q = 0; q < 5; q++) acc[a][q] = 0.f;
        #pragma unroll
        for (int d4 = 0; d4 < 16; d4++) {
            float4 kv[4], qv[5];
            #pragma unroll
            for (int a = 0; a < 4; a++) kv[a] = Ks4[(kg*4 + a)*17 + d4];
            #pragma unroll
            for (int q = 0; q < 5; q++) qv[q] = Qs4[(ug*5 + q)*17 + d4];
            #pragma unroll
            for (int a = 0; a < 4; a++)
                #pragma unroll
                for (int q = 0; q < 5; q++)
                    acc[a][q] += kv[a].x*qv[q].x + kv[a].y*qv[q].y
                               + kv[a].z*qv[q].z + kv[a].w*qv[q].w;
        }
        #pragma unroll
        for (int a = 0; a < 4; a++)
            #pragma unroll
            for (int q = 0; q < 5; q++)
                psm[(kg*4 + a)*44 + ug*5 + q] = acc[a][q] * SCALE;
    }
    __syncthreads();

    if (tid < UU) {
        float m = -INFINITY;
        #pragma unroll 8
        for (int k = 0; k < K3_CHUNK; k++) m = fmaxf(m, psm[k*44 + tid]);
        sm_m[tid] = m;
    }
    __syncthreads();
    #pragma unroll
    for (int it = 0; it < 20; it++) {                 // 2560 exps
        int i = tid + it*128;
        int k = i / 40, u = i - k*40;
        psm[k*44 + u] = __expf(psm[k*44 + u] - sm_m[u]);
    }
    __syncthreads();

    #pragma unroll
    for (int it = 0; it < 8; it++) {                  // V chunk (reuse Ks)
        int i = tid + it*128;
        int k = i >> 4, d4 = i & 15;
        Ks4[k*17 + d4] = Vg[((b*LL + k0 + k)*HH + h)*16 + d4];
    }
    if (tid < UU) {
        float s = 0.f;
        #pragma unroll 8
        for (int k = 0; k < K3_CHUNK; k++) s += psm[k*44 + tid];
        int pidx = (bh*K3_NCH + c)*UU + tid;
        g_pm[pidx] = sm_m[tid];
        g_pl[pidx] = s;
    }
    __syncthreads();

    // ---- AV ----
    {
        int dg = tid & 15, ug = tid >> 4;
        float4 oacc[5];
        #pragma unroll
        for (int j = 0; j < 5; j++) oacc[j] = make_float4(0.f, 0.f, 0.f, 0.f);
        #pragma unroll 8
        for (int k = 0; k < K3_CHUNK; k++) {
            float4 vv = Ks4[k*17 + dg];
            float p[5];
            #pragma unroll
            for (int j = 0; j < 5; j++) p[j] = psm[k*44 + ug*5 + j];
            #pragma unroll
            for (int j = 0; j < 5; j++) {
                oacc[j].x += p[j]*vv.x; oacc[j].y += p[j]*vv.y;
                oacc[j].z += p[j]*vv.z; oacc[j].w += p[j]*vv.w;
            }
        }
        float4* dst = (float4*)(g_pacc + ((size_t)(bh*K3_NCH + c)*UU)*DD);
        #pragma unroll
        for (int j = 0; j < 5; j++)
            dst[(ug*5 + j)*16 + dg] = oacc[j];
    }
}

// ================= Kernel 3b: combine chunk partials (LSE merge, 4-way ILP) ====
__global__ void __launch_bounds__(64) k_combine() {
    int u  = blockIdx.x % UU;
    int bh = blockIdx.x / UU;
    int d  = threadIdx.x;
    int base = bh*K3_NCH*UU + u;
    float m = -INFINITY;
    #pragma unroll
    for (int c = 0; c < K3_NCH; c++) m = fmaxf(m, g_pm[base + c*UU]);
    float ls = 0.f, v0 = 0.f, v1 = 0.f, v2 = 0.f, v3 = 0.f;
    #pragma unroll
    for (int c = 0; c < K3_NCH; c += 4) {
        float w0 = __expf(g_pm[base + (c+0)*UU] - m);
        float w1 = __expf(g_pm[base + (c+1)*UU] - m);
        float w2 = __expf(g_pm[base + (c+2)*UU] - m);
        float w3 = __expf(g_pm[base + (c+3)*UU] - m);
        ls += g_pl[base + (c+0)*UU]*w0 + g_pl[base + (c+1)*UU]*w1
            + g_pl[base + (c+2)*UU]*w2 + g_pl[base + (c+3)*UU]*w3;
        v0 += g_pacc[(size_t)(base + (c+0)*UU)*DD + d]*w0;
        v1 += g_pacc[(size_t)(base + (c+1)*UU)*DD + d]*w1;
        v2 += g_pacc[(size_t)(base + (c+2)*UU)*DD + d]*w2;
        v3 += g_pacc[(size_t)(base + (c+3)*UU)*DD + d]*w3;
    }
    g_upd[(bh*UU + u)*DD + d] = (v0 + v1 + v2 + v3) / ls;
}

// ================= Kernel 4a: per-chunk sums of V along L ====
__global__ void k_csum(const float* __restrict__ V) {
    int b = blockIdx.x >> 4;
    int c = blockIdx.x & 15;
    int hd = threadIdx.x;
    const float* p = V + ((size_t)(b*LL + c*K4_CLEN))*512 + hd;
    float s = 0.f;
    #pragma unroll 8
    for (int i = 0; i < K4_CLEN; i++) s += p[i*512];
    g_csum[(b*K4_NC + c)*512 + hd] = s;
}

// ================= Kernel 4b: cumsum + scatter upd -> output ====
__global__ void k_out(const float* __restrict__ V, float* __restrict__ out) {
    int b = blockIdx.x >> 4;
    int c = blockIdx.x & 15;
    int hd = threadIdx.x;
    int h = hd >> 6, d = hd & 63;
    float acc = 0.f;
    for (int cc = 0; cc < c; cc++) acc += g_csum[(b*K4_NC + cc)*512 + hd];
    const float* p = V   + ((size_t)(b*LL + c*K4_CLEN))*512 + hd;
    float*       q = out + ((size_t)(b*LL + c*K4_CLEN))*512 + hd;
    const int* sel = g_sel + (b*HH + h)*LL + c*K4_CLEN;
    for (int i = 0; i < K4_CLEN; i++) {
        acc += p[i*512];
        int se = sel[i];
        float v = acc;
        if (se >= 0) v = g_upd[((b*HH + h)*UU + se)*DD + d];
        q[i*512] = v;
    }
}

// ================= launch ====
extern "C" void kernel_launch(void* const* d_in, const int* in_sizes, int n_in,
                              void* d_out, int out_size) {
    const float* Q  = (const float*)d_in[0];
    const float* K  = (const float*)d_in[1];
    const float* V  = (const float*)d_in[2];
    const int* idx  = (const int*)d_in[3];
    float* out = (float*)d_out;

    k_M<<<BB*HH*LL/4, 256>>>(Q, K, idx);
    k_topk<<<BB*HH, 256>>>();
    dim3 g3(K3_NCH, BB*HH);
    k_attn_partial<<<g3, K3_T>>>(Q, K, V);
    k_combine<<<BB*HH*UU, DD>>>();
    k_csum<<<BB*K4_NC, 512>>>(V);
    k_out<<<BB*K4_NC, 512>>>(V, out);
}